// round 4
// baseline (speedup 1.0000x reference)
#include <cuda_runtime.h>
#include <math.h>

#define NN   100000
#define EE   1600000
#define DD   128
#define GG   128
#define LL   4
#define NCLS 10
#define EPSV 1e-5f

// ---------------- scratch (static device globals; no allocation) ----------------
static __device__ __align__(16) float g_h [(size_t)NN * DD];   // GEMM output (gather source)
static __device__ __align__(16) float g_h2[(size_t)NN * DD];   // SpMM output
static __device__ __align__(16) float g_am[GG * DD];           // alpha * mean
static __device__ __align__(16) float g_wr[GG * DD];           // gn_weight * rstd
static __device__ __align__(16) float g_we[EE];
static __device__ __align__(16) float g_dis[NN];
static __device__ int   g_src[EE];
static __device__ int   g_dst[EE];
static __device__ int   g_batch[NN];
static __device__ int   g_cnt[NN];
static __device__ int   g_fill[NN];
static __device__ int   g_rowptr[NN + 1];
static __device__ int   g_col[EE];
static __device__ int   g_gcnt[GG];
static __device__ int   g_gptr[GG + 1];
static __device__ int   g_i64;

// ---------------- dtype detection: int64 vs int32 index buffers ----------------
__global__ void k_detect(const int* __restrict__ eiw) {
    __shared__ int bad;
    if (threadIdx.x == 0) bad = 0;
    __syncthreads();
    // If int64 (little-endian, values in [0,1e5)), every odd 32-bit word is 0.
    for (int i = threadIdx.x; i < 2048; i += blockDim.x)
        if (eiw[2 * i + 1] != 0) bad = 1;
    __syncthreads();
    if (threadIdx.x == 0) g_i64 = bad ? 0 : 1;
}

// ---------------- preprocessing ----------------
__global__ void k_init() {
    int i = blockIdx.x * blockDim.x + threadIdx.x;
    int stride = gridDim.x * blockDim.x;
    for (int n = i; n < NN; n += stride) { g_cnt[n] = 0; g_fill[n] = 0; }
    if (i < GG) g_gcnt[i] = 0;
}

__global__ void k_cvt_edges(const void* __restrict__ ei) {
    int e = blockIdx.x * blockDim.x + threadIdx.x;
    if (e >= EE) return;
    int s, d;
    if (g_i64) {
        const long long* p = (const long long*)ei;
        s = (int)p[e]; d = (int)p[EE + e];
    } else {
        const int* p = (const int*)ei;
        s = p[e]; d = p[EE + e];
    }
    if ((unsigned)s >= NN) s = 0;
    if ((unsigned)d >= NN) d = 0;
    g_src[e] = s; g_dst[e] = d;
    atomicAdd(&g_cnt[d], 1);
}

__global__ void k_cvt_batch(const void* __restrict__ batch) {
    int n = blockIdx.x * blockDim.x + threadIdx.x;
    if (n >= NN) return;
    int b;
    if (g_i64) b = (int)((const long long*)batch)[n];
    else       b = ((const int*)batch)[n];
    if ((unsigned)b >= GG) b = 0;
    g_batch[n] = b;
    atomicAdd(&g_gcnt[b], 1);
}

__global__ void k_deg() {
    int n = blockIdx.x * blockDim.x + threadIdx.x;
    if (n < NN) g_dis[n] = rsqrtf((float)(g_cnt[n] + 1));
}

// simple chunked exclusive scan: 1 block, 256 threads, 400 elems per thread.
#define SCAN_CH 400
__global__ void k_scan() {
    __shared__ int ssum[256];
    int t = threadIdx.x;
    int lo = t * SCAN_CH;
    int hi = lo + SCAN_CH; if (hi > NN) hi = NN;
    int s = 0;
    for (int i = lo; i < hi; i++) s += g_cnt[i];
    ssum[t] = s;
    __syncthreads();
    if (t == 0) {
        int r = 0;
        for (int i = 0; i < 256; i++) { int v = ssum[i]; ssum[i] = r; r += v; }
        g_rowptr[NN] = EE;
    }
    __syncthreads();
    int run = ssum[t];
    for (int i = lo; i < hi; i++) { g_rowptr[i] = run; run += g_cnt[i]; }
}

__global__ void k_gscan() {
    int r = 0;
    for (int i = 0; i < GG; i++) { g_gptr[i] = r; r += g_gcnt[i]; }
    g_gptr[GG] = r;
}

__global__ void k_scatter() {
    int e = blockIdx.x * blockDim.x + threadIdx.x;
    if (e >= EE) return;
    int s = g_src[e], d = g_dst[e];
    int pos = g_rowptr[d] + atomicAdd(&g_fill[d], 1);
    g_col[pos] = s;
    g_we[pos]  = g_dis[s] * g_dis[d];
}

// ---------------- GEMM: g_h = X @ W  (X [NN,128], W [128,128]) ----------------
// 256 threads/block; 64 rows x 128 cols per block; X tile transposed in smem,
// W staged in 16-wide k chunks. Static smem = 34816 + 8192 = 43008 B.
__global__ void __launch_bounds__(256) k_gemm(const float* __restrict__ X,
                                              const float* __restrict__ W) {
    __shared__ __align__(16) float xsT[128][68];  // [k][row(+pad)]
    __shared__ __align__(16) float ws[16][128];   // k-chunk of W
    int tid  = threadIdx.x;
    int row0 = blockIdx.x * 64;

    const float4* X4 = (const float4*)X;
    for (int t = tid; t < 64 * 32; t += 256) {
        int r = t >> 5, c4 = t & 31;
        float4 v = make_float4(0.f, 0.f, 0.f, 0.f);
        int m = row0 + r;
        if (m < NN) v = X4[(size_t)m * 32 + c4];
        int c = c4 * 4;
        xsT[c + 0][r] = v.x;
        xsT[c + 1][r] = v.y;
        xsT[c + 2][r] = v.z;
        xsT[c + 3][r] = v.w;
    }

    int tm = tid & 15, tn = tid >> 4;   // tm: 16 row-groups of 4; tn: 16 col-groups of 8
    float acc[4][8];
    #pragma unroll
    for (int i = 0; i < 4; i++)
        #pragma unroll
        for (int j = 0; j < 8; j++) acc[i][j] = 0.f;

    const float4* W4 = (const float4*)W;
    for (int kc = 0; kc < 8; kc++) {
        __syncthreads();
        float4* ws4 = (float4*)&ws[0][0];
        #pragma unroll
        for (int i = 0; i < 2; i++) ws4[tid + i * 256] = W4[kc * 512 + tid + i * 256];
        __syncthreads();
        #pragma unroll
        for (int k = 0; k < 16; k++) {
            int kk = kc * 16 + k;
            float4 av = *(const float4*)&xsT[kk][tm * 4];
            float4 b0 = *(const float4*)&ws[k][tn * 8];
            float4 b1 = *(const float4*)&ws[k][tn * 8 + 4];
            float a[4] = {av.x, av.y, av.z, av.w};
            float b[8] = {b0.x, b0.y, b0.z, b0.w, b1.x, b1.y, b1.z, b1.w};
            #pragma unroll
            for (int i = 0; i < 4; i++)
                #pragma unroll
                for (int j = 0; j < 8; j++)
                    acc[i][j] = fmaf(a[i], b[j], acc[i][j]);
        }
    }

    float4* Y4 = (float4*)g_h;
    #pragma unroll
    for (int i = 0; i < 4; i++) {
        int m = row0 + tm * 4 + i;
        if (m < NN) {
            Y4[(size_t)m * 32 + tn * 2]     = make_float4(acc[i][0], acc[i][1], acc[i][2], acc[i][3]);
            Y4[(size_t)m * 32 + tn * 2 + 1] = make_float4(acc[i][4], acc[i][5], acc[i][6], acc[i][7]);
        }
    }
}

// ---------------- SpMM: g_h2[d] = bias + selfw*h[d] + sum_e w[e]*h[col[e]] ----------------
__global__ void k_spmm(const float* __restrict__ bias) {
    int n    = (blockIdx.x * blockDim.x + threadIdx.x) >> 5;
    int lane = threadIdx.x & 31;
    if (n >= NN) return;
    const float4* h4 = (const float4*)g_h;
    float4 acc = ((const float4*)bias)[lane];
    float dn = g_dis[n];
    float sw = dn * dn;
    float4 hv = h4[(size_t)n * 32 + lane];
    acc.x = fmaf(sw, hv.x, acc.x);
    acc.y = fmaf(sw, hv.y, acc.y);
    acc.z = fmaf(sw, hv.z, acc.z);
    acc.w = fmaf(sw, hv.w, acc.w);
    int s = g_rowptr[n], e = g_rowptr[n + 1];
    int i = s;
    for (; i + 2 <= e; i += 2) {
        int   c0 = g_col[i],  c1 = g_col[i + 1];
        float w0 = g_we[i],   w1 = g_we[i + 1];
        float4 v0 = h4[(size_t)c0 * 32 + lane];
        float4 v1 = h4[(size_t)c1 * 32 + lane];
        acc.x = fmaf(w0, v0.x, acc.x); acc.y = fmaf(w0, v0.y, acc.y);
        acc.z = fmaf(w0, v0.z, acc.z); acc.w = fmaf(w0, v0.w, acc.w);
        acc.x = fmaf(w1, v1.x, acc.x); acc.y = fmaf(w1, v1.y, acc.y);
        acc.z = fmaf(w1, v1.z, acc.z); acc.w = fmaf(w1, v1.w, acc.w);
    }
    if (i < e) {
        int c0 = g_col[i]; float w0 = g_we[i];
        float4 v0 = h4[(size_t)c0 * 32 + lane];
        acc.x = fmaf(w0, v0.x, acc.x); acc.y = fmaf(w0, v0.y, acc.y);
        acc.z = fmaf(w0, v0.z, acc.z); acc.w = fmaf(w0, v0.w, acc.w);
    }
    ((float4*)g_h2)[(size_t)n * 32 + lane] = acc;
}

// ---------------- GraphNorm stats: block per graph, thread per feature ----------------
__global__ void k_stats(const float* __restrict__ alpha, const float* __restrict__ gw) {
    int g = blockIdx.x, d = threadIdx.x;
    int s = g_gptr[g], e = g_gptr[g + 1];
    int cnt = e - s;
    if (cnt <= 0) { g_am[g * DD + d] = 0.f; g_wr[g * DD + d] = 0.f; return; }
    const float* p = g_h2 + (size_t)s * DD + d;
    float s0 = 0, s1 = 0, s2 = 0, s3 = 0;
    int n = 0;
    for (; n + 4 <= cnt; n += 4) {
        s0 += p[(size_t)(n + 0) * DD];
        s1 += p[(size_t)(n + 1) * DD];
        s2 += p[(size_t)(n + 2) * DD];
        s3 += p[(size_t)(n + 3) * DD];
    }
    for (; n < cnt; n++) s0 += p[(size_t)n * DD];
    float mean = (s0 + s1 + s2 + s3) / (float)cnt;
    float am = alpha[d] * mean;
    float v0 = 0, v1 = 0, v2 = 0, v3 = 0;
    n = 0;
    for (; n + 4 <= cnt; n += 4) {
        float t0 = p[(size_t)(n + 0) * DD] - am;
        float t1 = p[(size_t)(n + 1) * DD] - am;
        float t2 = p[(size_t)(n + 2) * DD] - am;
        float t3 = p[(size_t)(n + 3) * DD] - am;
        v0 = fmaf(t0, t0, v0); v1 = fmaf(t1, t1, v1);
        v2 = fmaf(t2, t2, v2); v3 = fmaf(t3, t3, v3);
    }
    for (; n < cnt; n++) { float t = p[(size_t)n * DD] - am; v0 = fmaf(t, t, v0); }
    float var = (v0 + v1 + v2 + v3) / (float)cnt;
    g_am[g * DD + d] = am;
    g_wr[g * DD + d] = gw[d] * rsqrtf(var + EPSV);
}

// ---------------- normalize + ELU + residual -> out (x) ----------------
__global__ void k_apply(const float* __restrict__ xres, const float* __restrict__ gnb,
                        float* __restrict__ out) {
    int t = blockIdx.x * blockDim.x + threadIdx.x;
    if (t >= NN * 32) return;
    int n = t >> 5, q = t & 31;
    int g = g_batch[n];
    float4 h = ((const float4*)g_h2)[t];
    float4 a = ((const float4*)g_am)[g * 32 + q];
    float4 w = ((const float4*)g_wr)[g * 32 + q];
    float4 b = ((const float4*)gnb)[q];
    float4 r = ((const float4*)xres)[t];
    float4 o;
    float v;
    v = (h.x - a.x) * w.x + b.x; o.x = (v > 0.f ? v : expm1f(v)) + r.x;
    v = (h.y - a.y) * w.y + b.y; o.y = (v > 0.f ? v : expm1f(v)) + r.y;
    v = (h.z - a.z) * w.z + b.z; o.z = (v > 0.f ? v : expm1f(v)) + r.z;
    v = (h.w - a.w) * w.w + b.w; o.w = (v > 0.f ? v : expm1f(v)) + r.w;
    ((float4*)out)[t] = o;
}

// ---------------- fused pool + MLP head ----------------
__global__ void k_mlp(const float* __restrict__ x, const float* __restrict__ w1,
                      const float* __restrict__ b1, const float* __restrict__ bng,
                      const float* __restrict__ bnb, const float* __restrict__ bnm,
                      const float* __restrict__ bnv, const float* __restrict__ w2,
                      const float* __restrict__ b2, float* __restrict__ out) {
    int g = blockIdx.x, d = threadIdx.x;
    __shared__ float p[DD], z1[DD];
    int s = g_gptr[g], e = g_gptr[g + 1];
    int cnt = e - s, n = 0;
    const float* xp = x + (size_t)s * DD + d;
    float s0 = 0, s1 = 0, s2 = 0, s3 = 0;
    for (; n + 4 <= cnt; n += 4) {
        s0 += xp[(size_t)(n + 0) * DD];
        s1 += xp[(size_t)(n + 1) * DD];
        s2 += xp[(size_t)(n + 2) * DD];
        s3 += xp[(size_t)(n + 3) * DD];
    }
    for (; n < cnt; n++) s0 += xp[(size_t)n * DD];
    p[d] = s0 + s1 + s2 + s3;
    __syncthreads();
    float z = b1[d];
    #pragma unroll 4
    for (int k = 0; k < DD; k++) z = fmaf(p[k], w1[k * DD + d], z);
    z = bng[d] * (z - bnm[d]) * rsqrtf(bnv[d] + EPSV) + bnb[d];
    z = z > 0.f ? z : 0.f;
    z1[d] = z;
    __syncthreads();
    if (d < NCLS) {
        float o = b2[d];
        #pragma unroll 4
        for (int k = 0; k < DD; k++) o = fmaf(z1[k], w2[k * NCLS + d], o);
        out[(size_t)NN * DD + g * NCLS + d] = o;
    }
}

// ---------------- launch ----------------
extern "C" void kernel_launch(void* const* d_in, const int* in_sizes, int n_in,
                              void* d_out, int out_size) {
    const float* x0     = (const float*)d_in[0];
    const void*  ei     = d_in[1];
    const void*  batch  = d_in[2];
    const float* conv_w = (const float*)d_in[3];
    const float* conv_b = (const float*)d_in[4];
    const float* gn_w   = (const float*)d_in[5];
    const float* gn_b   = (const float*)d_in[6];
    const float* gn_ms  = (const float*)d_in[7];
    const float* w1     = (const float*)d_in[8];
    const float* b1     = (const float*)d_in[9];
    const float* bng    = (const float*)d_in[10];
    const float* bnb    = (const float*)d_in[11];
    const float* bnm    = (const float*)d_in[12];
    const float* bnv    = (const float*)d_in[13];
    const float* w2     = (const float*)d_in[14];
    const float* b2     = (const float*)d_in[15];
    float* out = (float*)d_out;

    k_detect<<<1, 256>>>((const int*)ei);
    k_init<<<256, 256>>>();
    k_cvt_edges<<<(EE + 255) / 256, 256>>>(ei);
    k_cvt_batch<<<(NN + 255) / 256, 256>>>(batch);
    k_deg<<<(NN + 255) / 256, 256>>>();
    k_scan<<<1, 256>>>();
    k_gscan<<<1, 1>>>();
    k_scatter<<<(EE + 255) / 256, 256>>>();

    const float* xin = x0;
    for (int l = 0; l < LL; l++) {
        k_gemm<<<(NN + 63) / 64, 256>>>(xin, conv_w + (size_t)l * DD * DD);
        k_spmm<<<(NN + 7) / 8, 256>>>(conv_b + (size_t)l * DD);
        k_stats<<<GG, DD>>>(gn_ms + (size_t)l * DD, gn_w + (size_t)l * DD);
        k_apply<<<(NN * 32 + 255) / 256, 256>>>(xin, gn_b + (size_t)l * DD, out);
        xin = out;
    }
    k_mlp<<<GG, DD>>>(out, w1, b1, bng, bnb, bnm, bnv, w2, b2, out);
}

// round 5
// speedup vs baseline: 1.3008x; 1.3008x over previous
#include <cuda_runtime.h>
#include <math.h>

#define NN   100000
#define EE   1600000
#define DD   128
#define GG   128
#define LL   4
#define NCLS 10
#define EPSV 1e-5f

// ---------------- scratch (static device globals; no allocation) ----------------
static __device__ __align__(16) float g_h [(size_t)NN * DD];   // GEMM output (gather source)
static __device__ __align__(16) float g_h2[(size_t)NN * DD];   // SpMM output
static __device__ __align__(16) float g_am[GG * DD];           // alpha * mean
static __device__ __align__(16) float g_wr[GG * DD];           // gn_weight * rstd
static __device__ __align__(16) float g_we[EE];
static __device__ __align__(16) float g_dis[NN];
static __device__ int   g_src[EE];
static __device__ int   g_dst[EE];
static __device__ int   g_batch[NN];
static __device__ int   g_cnt[NN];
static __device__ int   g_fill[NN];
static __device__ int   g_rowptr[NN + 1];
static __device__ int   g_col[EE];
static __device__ int   g_gptr[GG + 1];
static __device__ int   g_i64;

union F4U64 { float4 f; unsigned long long u[2]; float s[4]; };

// ---------------- dtype detection: int64 vs int32 index buffers ----------------
__global__ void k_detect(const int* __restrict__ eiw) {
    __shared__ int bad;
    if (threadIdx.x == 0) bad = 0;
    __syncthreads();
    // If int64 (little-endian, values in [0,1e5)), every odd 32-bit word is 0.
    for (int i = threadIdx.x; i < 2048; i += blockDim.x)
        if (eiw[2 * i + 1] != 0) bad = 1;
    __syncthreads();
    if (threadIdx.x == 0) g_i64 = bad ? 0 : 1;
}

// ---------------- preprocessing ----------------
__global__ void k_init() {
    int i = blockIdx.x * blockDim.x + threadIdx.x;
    int stride = gridDim.x * blockDim.x;
    for (int n = i; n < NN; n += stride) { g_cnt[n] = 0; g_fill[n] = 0; }
}

__global__ void k_cvt_edges(const void* __restrict__ ei) {
    int e = blockIdx.x * blockDim.x + threadIdx.x;
    if (e >= EE) return;
    int s, d;
    if (g_i64) {
        const long long* p = (const long long*)ei;
        s = (int)p[e]; d = (int)p[EE + e];
    } else {
        const int* p = (const int*)ei;
        s = p[e]; d = p[EE + e];
    }
    if ((unsigned)s >= NN) s = 0;
    if ((unsigned)d >= NN) d = 0;
    g_src[e] = s; g_dst[e] = d;
    atomicAdd(&g_cnt[d], 1);
}

// batch is sorted: derive g_gptr from boundaries, no atomics.
__global__ void k_cvt_batch(const void* __restrict__ batch) {
    int n = blockIdx.x * blockDim.x + threadIdx.x;
    if (n >= NN) return;
    int b, bp = -1;
    if (g_i64) {
        const long long* p = (const long long*)batch;
        b = (int)p[n];
        if (n > 0) bp = (int)p[n - 1];
    } else {
        const int* p = (const int*)batch;
        b = p[n];
        if (n > 0) bp = p[n - 1];
    }
    if ((unsigned)b >= GG) b = 0;
    if (n > 0 && (unsigned)bp >= GG) bp = 0;
    g_batch[n] = b;
    if (b != bp)
        for (int g = bp + 1; g <= b; g++) g_gptr[g] = n;
    if (n == NN - 1)
        for (int g = b + 1; g <= GG; g++) g_gptr[g] = NN;
}

__global__ void k_deg() {
    int n = blockIdx.x * blockDim.x + threadIdx.x;
    if (n < NN) g_dis[n] = rsqrtf((float)(g_cnt[n] + 1));
}

// simple chunked exclusive scan: 1 block, 256 threads, 400 elems per thread.
#define SCAN_CH 400
__global__ void k_scan() {
    __shared__ int ssum[256];
    int t = threadIdx.x;
    int lo = t * SCAN_CH;
    int hi = lo + SCAN_CH; if (hi > NN) hi = NN;
    int s = 0;
    for (int i = lo; i < hi; i++) s += g_cnt[i];
    ssum[t] = s;
    __syncthreads();
    if (t == 0) {
        int r = 0;
        for (int i = 0; i < 256; i++) { int v = ssum[i]; ssum[i] = r; r += v; }
        g_rowptr[NN] = EE;
    }
    __syncthreads();
    int run = ssum[t];
    for (int i = lo; i < hi; i++) { g_rowptr[i] = run; run += g_cnt[i]; }
}

__global__ void k_scatter() {
    int e = blockIdx.x * blockDim.x + threadIdx.x;
    if (e >= EE) return;
    int s = g_src[e], d = g_dst[e];
    int pos = g_rowptr[d] + atomicAdd(&g_fill[d], 1);
    g_col[pos] = s;
    g_we[pos]  = g_dis[s] * g_dis[d];
}

// ---------------- GEMM: g_h = X @ W  via packed fma.rn.f32x2 ----------------
// 256 threads/block; 64 rows x 128 cols per block; X tile transposed in smem,
// W staged in 16-wide k chunks. 16 FFMA2 per k-step per thread.
__global__ void __launch_bounds__(256) k_gemm(const float* __restrict__ X,
                                              const float* __restrict__ W) {
    __shared__ __align__(16) float xsT[128][68];  // [k][row(+pad)]
    __shared__ __align__(16) float ws[16][128];   // k-chunk of W
    int tid  = threadIdx.x;
    int row0 = blockIdx.x * 64;

    const float4* X4 = (const float4*)X;
    for (int t = tid; t < 64 * 32; t += 256) {
        int r = t >> 5, c4 = t & 31;
        float4 v = make_float4(0.f, 0.f, 0.f, 0.f);
        int m = row0 + r;
        if (m < NN) v = X4[(size_t)m * 32 + c4];
        int c = c4 * 4;
        xsT[c + 0][r] = v.x;
        xsT[c + 1][r] = v.y;
        xsT[c + 2][r] = v.z;
        xsT[c + 3][r] = v.w;
    }

    int tm = tid & 15, tn = tid >> 4;   // tm: 16 row-groups of 4; tn: 16 col-groups of 8
    unsigned long long acc2[4][4];      // [row][feat-pair]
    #pragma unroll
    for (int i = 0; i < 4; i++)
        #pragma unroll
        for (int j = 0; j < 4; j++) acc2[i][j] = 0ull;

    const float4* W4 = (const float4*)W;
    for (int kc = 0; kc < 8; kc++) {
        __syncthreads();
        float4* ws4 = (float4*)&ws[0][0];
        #pragma unroll
        for (int i = 0; i < 2; i++) ws4[tid + i * 256] = W4[kc * 512 + tid + i * 256];
        __syncthreads();
        #pragma unroll
        for (int k = 0; k < 16; k++) {
            int kk = kc * 16 + k;
            F4U64 av, b0, b1;
            av.f = *(const float4*)&xsT[kk][tm * 4];
            b0.f = *(const float4*)&ws[k][tn * 8];
            b1.f = *(const float4*)&ws[k][tn * 8 + 4];
            unsigned long long bv[4] = {b0.u[0], b0.u[1], b1.u[0], b1.u[1]};
            #pragma unroll
            for (int i = 0; i < 4; i++) {
                unsigned int au = __float_as_uint(av.s[i]);
                unsigned long long a2;
                asm("mov.b64 %0, {%1, %1};" : "=l"(a2) : "r"(au));
                #pragma unroll
                for (int j = 0; j < 4; j++)
                    asm("fma.rn.f32x2 %0, %1, %2, %0;"
                        : "+l"(acc2[i][j]) : "l"(a2), "l"(bv[j]));
            }
        }
    }

    float4* Y4 = (float4*)g_h;
    #pragma unroll
    for (int i = 0; i < 4; i++) {
        int m = row0 + tm * 4 + i;
        if (m < NN) {
            F4U64 o0, o1;
            o0.u[0] = acc2[i][0]; o0.u[1] = acc2[i][1];
            o1.u[0] = acc2[i][2]; o1.u[1] = acc2[i][3];
            Y4[(size_t)m * 32 + tn * 2]     = o0.f;
            Y4[(size_t)m * 32 + tn * 2 + 1] = o1.f;
        }
    }
}

// ---------------- SpMM: g_h2[d] = bias + selfw*h[d] + sum_e w[e]*h[col[e]] ----------------
__global__ void k_spmm(const float* __restrict__ bias) {
    int n    = (blockIdx.x * blockDim.x + threadIdx.x) >> 5;
    int lane = threadIdx.x & 31;
    if (n >= NN) return;
    const float4* h4 = (const float4*)g_h;
    float4 acc = ((const float4*)bias)[lane];
    float dn = g_dis[n];
    float sw = dn * dn;
    float4 hv = h4[(size_t)n * 32 + lane];
    acc.x = fmaf(sw, hv.x, acc.x);
    acc.y = fmaf(sw, hv.y, acc.y);
    acc.z = fmaf(sw, hv.z, acc.z);
    acc.w = fmaf(sw, hv.w, acc.w);
    int s = g_rowptr[n], e = g_rowptr[n + 1];
    int i = s;
    for (; i + 4 <= e; i += 4) {
        int   c0 = g_col[i],     c1 = g_col[i + 1];
        int   c2 = g_col[i + 2], c3 = g_col[i + 3];
        float w0 = g_we[i],      w1 = g_we[i + 1];
        float w2 = g_we[i + 2],  w3 = g_we[i + 3];
        float4 v0 = h4[(size_t)c0 * 32 + lane];
        float4 v1 = h4[(size_t)c1 * 32 + lane];
        float4 v2 = h4[(size_t)c2 * 32 + lane];
        float4 v3 = h4[(size_t)c3 * 32 + lane];
        acc.x = fmaf(w0, v0.x, acc.x); acc.y = fmaf(w0, v0.y, acc.y);
        acc.z = fmaf(w0, v0.z, acc.z); acc.w = fmaf(w0, v0.w, acc.w);
        acc.x = fmaf(w1, v1.x, acc.x); acc.y = fmaf(w1, v1.y, acc.y);
        acc.z = fmaf(w1, v1.z, acc.z); acc.w = fmaf(w1, v1.w, acc.w);
        acc.x = fmaf(w2, v2.x, acc.x); acc.y = fmaf(w2, v2.y, acc.y);
        acc.z = fmaf(w2, v2.z, acc.z); acc.w = fmaf(w2, v2.w, acc.w);
        acc.x = fmaf(w3, v3.x, acc.x); acc.y = fmaf(w3, v3.y, acc.y);
        acc.z = fmaf(w3, v3.z, acc.z); acc.w = fmaf(w3, v3.w, acc.w);
    }
    for (; i < e; i++) {
        int c0 = g_col[i]; float w0 = g_we[i];
        float4 v0 = h4[(size_t)c0 * 32 + lane];
        acc.x = fmaf(w0, v0.x, acc.x); acc.y = fmaf(w0, v0.y, acc.y);
        acc.z = fmaf(w0, v0.z, acc.z); acc.w = fmaf(w0, v0.w, acc.w);
    }
    ((float4*)g_h2)[(size_t)n * 32 + lane] = acc;
}

// ---------------- GraphNorm stats: one pass (sum + sumsq), 512 thr/block ----------------
__global__ void __launch_bounds__(512) k_stats(const float* __restrict__ alpha,
                                               const float* __restrict__ gw) {
    int g = blockIdx.x;
    int t = threadIdx.x;
    int d = t & 127, sl = t >> 7;             // 4 node-slices x 128 features
    int s = g_gptr[g], e = g_gptr[g + 1];
    int cnt = e - s;
    __shared__ float ssum[4][DD], ssq[4][DD];
    float sum = 0.f, sq = 0.f;
    const float* p = g_h2 + (size_t)s * DD + d;
    int n = sl;
    #pragma unroll 4
    for (; n < cnt; n += 4) {
        float v = p[(size_t)n * DD];
        sum += v; sq = fmaf(v, v, sq);
    }
    ssum[sl][d] = sum; ssq[sl][d] = sq;
    __syncthreads();
    if (t < DD) {
        if (cnt <= 0) { g_am[g * DD + d] = 0.f; g_wr[g * DD + d] = 0.f; return; }
        float S = ssum[0][d] + ssum[1][d] + ssum[2][d] + ssum[3][d];
        float Q = ssq[0][d]  + ssq[1][d]  + ssq[2][d]  + ssq[3][d];
        float inv = 1.f / (float)cnt;
        float mean = S * inv;
        float am = alpha[d] * mean;
        float var = fmaf(am, am, fmaf(-2.f * am, mean, Q * inv));
        g_am[g * DD + d] = am;
        g_wr[g * DD + d] = gw[d] * rsqrtf(var + EPSV);
    }
}

// ---------------- normalize + ELU + residual -> out (x) ----------------
__global__ void k_apply(const float* __restrict__ xres, const float* __restrict__ gnb,
                        float* __restrict__ out) {
    int t = blockIdx.x * blockDim.x + threadIdx.x;
    if (t >= NN * 32) return;
    int n = t >> 5, q = t & 31;
    int g = g_batch[n];
    float4 h = ((const float4*)g_h2)[t];
    float4 a = ((const float4*)g_am)[g * 32 + q];
    float4 w = ((const float4*)g_wr)[g * 32 + q];
    float4 b = ((const float4*)gnb)[q];
    float4 r = ((const float4*)xres)[t];
    float4 o;
    float v;
    v = (h.x - a.x) * w.x + b.x; o.x = (v > 0.f ? v : expm1f(v)) + r.x;
    v = (h.y - a.y) * w.y + b.y; o.y = (v > 0.f ? v : expm1f(v)) + r.y;
    v = (h.z - a.z) * w.z + b.z; o.z = (v > 0.f ? v : expm1f(v)) + r.z;
    v = (h.w - a.w) * w.w + b.w; o.w = (v > 0.f ? v : expm1f(v)) + r.w;
    ((float4*)out)[t] = o;
}

// ---------------- fused pool + MLP head ----------------
__global__ void k_mlp(const float* __restrict__ x, const float* __restrict__ w1,
                      const float* __restrict__ b1, const float* __restrict__ bng,
                      const float* __restrict__ bnb, const float* __restrict__ bnm,
                      const float* __restrict__ bnv, const float* __restrict__ w2,
                      const float* __restrict__ b2, float* __restrict__ out) {
    int g = blockIdx.x, d = threadIdx.x;
    __shared__ float p[DD], z1[DD];
    int s = g_gptr[g], e = g_gptr[g + 1];
    int cnt = e - s, n = 0;
    const float* xp = x + (size_t)s * DD + d;
    float s0 = 0, s1 = 0, s2 = 0, s3 = 0;
    for (; n + 4 <= cnt; n += 4) {
        s0 += xp[(size_t)(n + 0) * DD];
        s1 += xp[(size_t)(n + 1) * DD];
        s2 += xp[(size_t)(n + 2) * DD];
        s3 += xp[(size_t)(n + 3) * DD];
    }
    for (; n < cnt; n++) s0 += xp[(size_t)n * DD];
    p[d] = s0 + s1 + s2 + s3;
    __syncthreads();
    float z = b1[d];
    #pragma unroll 4
    for (int k = 0; k < DD; k++) z = fmaf(p[k], w1[k * DD + d], z);
    z = bng[d] * (z - bnm[d]) * rsqrtf(bnv[d] + EPSV) + bnb[d];
    z = z > 0.f ? z : 0.f;
    z1[d] = z;
    __syncthreads();
    if (d < NCLS) {
        float o = b2[d];
        #pragma unroll 4
        for (int k = 0; k < DD; k++) o = fmaf(z1[k], w2[k * NCLS + d], o);
        out[(size_t)NN * DD + g * NCLS + d] = o;
    }
}

// ---------------- launch ----------------
extern "C" void kernel_launch(void* const* d_in, const int* in_sizes, int n_in,
                              void* d_out, int out_size) {
    const float* x0     = (const float*)d_in[0];
    const void*  ei     = d_in[1];
    const void*  batch  = d_in[2];
    const float* conv_w = (const float*)d_in[3];
    const float* conv_b = (const float*)d_in[4];
    const float* gn_w   = (const float*)d_in[5];
    const float* gn_b   = (const float*)d_in[6];
    const float* gn_ms  = (const float*)d_in[7];
    const float* w1     = (const float*)d_in[8];
    const float* b1     = (const float*)d_in[9];
    const float* bng    = (const float*)d_in[10];
    const float* bnb    = (const float*)d_in[11];
    const float* bnm    = (const float*)d_in[12];
    const float* bnv    = (const float*)d_in[13];
    const float* w2     = (const float*)d_in[14];
    const float* b2     = (const float*)d_in[15];
    float* out = (float*)d_out;

    k_detect<<<1, 256>>>((const int*)ei);
    k_init<<<256, 256>>>();
    k_cvt_edges<<<(EE + 255) / 256, 256>>>(ei);
    k_cvt_batch<<<(NN + 255) / 256, 256>>>(batch);
    k_deg<<<(NN + 255) / 256, 256>>>();
    k_scan<<<1, 256>>>();
    k_scatter<<<(EE + 255) / 256, 256>>>();

    const float* xin = x0;
    for (int l = 0; l < LL; l++) {
        k_gemm<<<(NN + 63) / 64, 256>>>(xin, conv_w + (size_t)l * DD * DD);
        k_spmm<<<(NN + 7) / 8, 256>>>(conv_b + (size_t)l * DD);
        k_stats<<<GG, 512>>>(gn_ms + (size_t)l * DD, gn_w + (size_t)l * DD);
        k_apply<<<(NN * 32 + 255) / 256, 256>>>(xin, gn_b + (size_t)l * DD, out);
        xin = out;
    }
    k_mlp<<<GG, DD>>>(out, w1, b1, bng, bnb, bnm, bnv, w2, b2, out);
}

// round 8
// speedup vs baseline: 1.6425x; 1.2627x over previous
#include <cuda_runtime.h>
#include <math.h>

#define NN   100000
#define EE   1600000
#define DD   128
#define GG   128
#define LL   4
#define NCLS 10
#define EPSV 1e-5f
#define NB   391          // ceil(NN/256) scan blocks

// ---------------- scratch (static device globals; no allocation) ----------------
static __device__ __align__(16) float g_h [(size_t)NN * DD];   // GEMM output (gather source)
static __device__ __align__(16) float g_h2[(size_t)NN * DD];   // SpMM output
static __device__ __align__(16) float g_am[GG * DD];           // alpha * mean
static __device__ __align__(16) float g_wr[GG * DD];           // gn_weight * rstd
static __device__ __align__(16) float g_pool[GG * DD];         // pooled sums
static __device__ __align__(16) float g_we[EE];
static __device__ __align__(16) float g_dis[NN];
static __device__ int   g_batch[NN];
static __device__ int   g_cnt[NN];
static __device__ int   g_fill[NN];
static __device__ int   g_rowptr[NN + 1];
static __device__ int   g_col[EE];
static __device__ int   g_gptr[GG + 1];
static __device__ int   g_part[NB];
static __device__ int   g_i64;

union F4U64 { float4 f; unsigned long long u[2]; float s[4]; };

// ---------------- dtype detection: int64 vs int32 index buffers ----------------
__global__ void k_detect(const int* __restrict__ eiw) {
    __shared__ int bad;
    if (threadIdx.x == 0) bad = 0;
    __syncthreads();
    // If int64 (little-endian, values in [0,1e5)), every odd 32-bit word is 0.
    for (int i = threadIdx.x; i < 2048; i += blockDim.x)
        if (eiw[2 * i + 1] != 0) bad = 1;
    __syncthreads();
    if (threadIdx.x == 0) g_i64 = bad ? 0 : 1;
}

// ---------------- preprocessing ----------------
__global__ void k_init() {
    int i = blockIdx.x * blockDim.x + threadIdx.x;
    int stride = gridDim.x * blockDim.x;
    for (int n = i; n < NN; n += stride) { g_cnt[n] = 0; g_fill[n] = 0; }
}

__global__ void k_hist(const void* __restrict__ ei) {
    int e = blockIdx.x * blockDim.x + threadIdx.x;
    if (e >= EE) return;
    int d = g_i64 ? (int)((const long long*)ei)[EE + e] : ((const int*)ei)[EE + e];
    if ((unsigned)d >= NN) d = 0;
    atomicAdd(&g_cnt[d], 1);
}

// batch is sorted: derive g_gptr from boundaries, no atomics.
__global__ void k_cvt_batch(const void* __restrict__ batch) {
    int n = blockIdx.x * blockDim.x + threadIdx.x;
    if (n >= NN) return;
    int b, bp = -1;
    if (g_i64) {
        const long long* p = (const long long*)batch;
        b = (int)p[n];
        if (n > 0) bp = (int)p[n - 1];
    } else {
        const int* p = (const int*)batch;
        b = p[n];
        if (n > 0) bp = p[n - 1];
    }
    if ((unsigned)b >= GG) b = 0;
    if (n > 0 && (unsigned)bp >= GG) bp = 0;
    g_batch[n] = b;
    if (b != bp)
        for (int g = bp + 1; g <= b; g++) g_gptr[g] = n;
    if (n == NN - 1)
        for (int g = b + 1; g <= GG; g++) g_gptr[g] = NN;
}

// ---------------- parallel 3-step scan (also computes dis = rsqrt(deg)) -----------
__global__ void k_scan1() {
    __shared__ int sh[256];
    int b = blockIdx.x, t = threadIdx.x;
    int i = b * 256 + t;
    int v = (i < NN) ? g_cnt[i] : 0;
    if (i < NN) g_dis[i] = rsqrtf((float)(v + 1));
    sh[t] = v;
    __syncthreads();
    for (int o = 128; o > 0; o >>= 1) {
        if (t < o) sh[t] += sh[t + o];
        __syncthreads();
    }
    if (t == 0) g_part[b] = sh[0];
}
__global__ void k_scan2() {
    if (threadIdx.x == 0) {
        int r = 0;
        for (int i = 0; i < NB; i++) { int v = g_part[i]; g_part[i] = r; r += v; }
        g_rowptr[NN] = EE;
    }
}
__global__ void k_scan3() {
    __shared__ int sh[256];
    int b = blockIdx.x, t = threadIdx.x;
    int i = b * 256 + t;
    int v = (i < NN) ? g_cnt[i] : 0;
    sh[t] = v;
    __syncthreads();
    for (int o = 1; o < 256; o <<= 1) {
        int x = (t >= o) ? sh[t - o] : 0;
        __syncthreads();
        sh[t] += x;
        __syncthreads();
    }
    if (i < NN) g_rowptr[i] = g_part[b] + sh[t] - v;
}

__global__ void k_scatter(const void* __restrict__ ei) {
    int e = blockIdx.x * blockDim.x + threadIdx.x;
    if (e >= EE) return;
    int s, d;
    if (g_i64) {
        const long long* p = (const long long*)ei;
        s = (int)p[e]; d = (int)p[EE + e];
    } else {
        const int* p = (const int*)ei;
        s = p[e]; d = p[EE + e];
    }
    if ((unsigned)s >= NN) s = 0;
    if ((unsigned)d >= NN) d = 0;
    int pos = g_rowptr[d] + atomicAdd(&g_fill[d], 1);
    g_col[pos] = s;
    g_we[pos]  = g_dis[s] * g_dis[d];
}

// ---------------- GEMM: g_h = X @ W  via packed fma.rn.f32x2 ----------------
// 256 threads/block; 64 rows x 128 cols per block; X tile transposed in smem,
// W staged in 16-wide k chunks. 16 FFMA2 per k-step per thread.
__global__ void __launch_bounds__(256) k_gemm(const float* __restrict__ X,
                                              const float* __restrict__ W) {
    __shared__ __align__(16) float xsT[128][68];  // [k][row(+pad)]
    __shared__ __align__(16) float ws[16][128];   // k-chunk of W
    int tid  = threadIdx.x;
    int row0 = blockIdx.x * 64;

    const float4* X4 = (const float4*)X;
    for (int t = tid; t < 64 * 32; t += 256) {
        int r = t >> 5, c4 = t & 31;
        float4 v = make_float4(0.f, 0.f, 0.f, 0.f);
        int m = row0 + r;
        if (m < NN) v = X4[(size_t)m * 32 + c4];
        int c = c4 * 4;
        xsT[c + 0][r] = v.x;
        xsT[c + 1][r] = v.y;
        xsT[c + 2][r] = v.z;
        xsT[c + 3][r] = v.w;
    }

    int tm = tid & 15, tn = tid >> 4;   // tm: 16 row-groups of 4; tn: 16 col-groups of 8
    unsigned long long acc2[4][4];      // [row][feat-pair]
    #pragma unroll
    for (int i = 0; i < 4; i++)
        #pragma unroll
        for (int j = 0; j < 4; j++) acc2[i][j] = 0ull;

    const float4* W4 = (const float4*)W;
    for (int kc = 0; kc < 8; kc++) {
        __syncthreads();
        float4* ws4 = (float4*)&ws[0][0];
        #pragma unroll
        for (int i = 0; i < 2; i++) ws4[tid + i * 256] = W4[kc * 512 + tid + i * 256];
        __syncthreads();
        #pragma unroll
        for (int k = 0; k < 16; k++) {
            int kk = kc * 16 + k;
            F4U64 av, b0, b1;
            av.f = *(const float4*)&xsT[kk][tm * 4];
            b0.f = *(const float4*)&ws[k][tn * 8];
            b1.f = *(const float4*)&ws[k][tn * 8 + 4];
            unsigned long long bv[4] = {b0.u[0], b0.u[1], b1.u[0], b1.u[1]};
            #pragma unroll
            for (int i = 0; i < 4; i++) {
                unsigned int au = __float_as_uint(av.s[i]);
                unsigned long long a2;
                asm("mov.b64 %0, {%1, %1};" : "=l"(a2) : "r"(au));
                #pragma unroll
                for (int j = 0; j < 4; j++)
                    asm("fma.rn.f32x2 %0, %1, %2, %0;"
                        : "+l"(acc2[i][j]) : "l"(a2), "l"(bv[j]));
            }
        }
    }

    float4* Y4 = (float4*)g_h;
    #pragma unroll
    for (int i = 0; i < 4; i++) {
        int m = row0 + tm * 4 + i;
        if (m < NN) {
            F4U64 o0, o1;
            o0.u[0] = acc2[i][0]; o0.u[1] = acc2[i][1];
            o1.u[0] = acc2[i][2]; o1.u[1] = acc2[i][3];
            Y4[(size_t)m * 32 + tn * 2]     = o0.f;
            Y4[(size_t)m * 32 + tn * 2 + 1] = o1.f;
        }
    }
}

// ---------------- SpMM: g_h2[d] = bias + selfw*h[d] + sum_e w[e]*h[col[e]] ----------------
__global__ void k_spmm(const float* __restrict__ bias) {
    int n    = (blockIdx.x * blockDim.x + threadIdx.x) >> 5;
    int lane = threadIdx.x & 31;
    if (n >= NN) return;
    const float4* h4 = (const float4*)g_h;
    float4 acc = ((const float4*)bias)[lane];
    float dn = g_dis[n];
    float sw = dn * dn;
    float4 hv = h4[(size_t)n * 32 + lane];
    acc.x = fmaf(sw, hv.x, acc.x);
    acc.y = fmaf(sw, hv.y, acc.y);
    acc.z = fmaf(sw, hv.z, acc.z);
    acc.w = fmaf(sw, hv.w, acc.w);
    int s = g_rowptr[n], e = g_rowptr[n + 1];
    int i = s;
    for (; i + 4 <= e; i += 4) {
        int   c0 = g_col[i],     c1 = g_col[i + 1];
        int   c2 = g_col[i + 2], c3 = g_col[i + 3];
        float w0 = g_we[i],      w1 = g_we[i + 1];
        float w2 = g_we[i + 2],  w3 = g_we[i + 3];
        float4 v0 = h4[(size_t)c0 * 32 + lane];
        float4 v1 = h4[(size_t)c1 * 32 + lane];
        float4 v2 = h4[(size_t)c2 * 32 + lane];
        float4 v3 = h4[(size_t)c3 * 32 + lane];
        acc.x = fmaf(w0, v0.x, acc.x); acc.y = fmaf(w0, v0.y, acc.y);
        acc.z = fmaf(w0, v0.z, acc.z); acc.w = fmaf(w0, v0.w, acc.w);
        acc.x = fmaf(w1, v1.x, acc.x); acc.y = fmaf(w1, v1.y, acc.y);
        acc.z = fmaf(w1, v1.z, acc.z); acc.w = fmaf(w1, v1.w, acc.w);
        acc.x = fmaf(w2, v2.x, acc.x); acc.y = fmaf(w2, v2.y, acc.y);
        acc.z = fmaf(w2, v2.z, acc.z); acc.w = fmaf(w2, v2.w, acc.w);
        acc.x = fmaf(w3, v3.x, acc.x); acc.y = fmaf(w3, v3.y, acc.y);
        acc.z = fmaf(w3, v3.z, acc.z); acc.w = fmaf(w3, v3.w, acc.w);
    }
    for (; i < e; i++) {
        int c0 = g_col[i]; float w0 = g_we[i];
        float4 v0 = h4[(size_t)c0 * 32 + lane];
        acc.x = fmaf(w0, v0.x, acc.x); acc.y = fmaf(w0, v0.y, acc.y);
        acc.z = fmaf(w0, v0.z, acc.z); acc.w = fmaf(w0, v0.w, acc.w);
    }
    ((float4*)g_h2)[(size_t)n * 32 + lane] = acc;
}

// ---------------- GraphNorm stats: one pass, grid (GG, 4 feature-chunks) ----------------
// block: 256 threads = 8 node-slices x 32 features.
__global__ void __launch_bounds__(256) k_stats(const float* __restrict__ alpha,
                                               const float* __restrict__ gw) {
    int g = blockIdx.x;
    int fc = blockIdx.y;                      // feature chunk 0..3
    int t = threadIdx.x;
    int f = fc * 32 + (t & 31), sl = t >> 5;  // 8 slices
    int s = g_gptr[g], e = g_gptr[g + 1];
    int cnt = e - s;
    __shared__ float ssum[8][32], ssq[8][32];
    float sum = 0.f, sq = 0.f;
    const float* p = g_h2 + (size_t)s * DD + f;
    #pragma unroll 4
    for (int n = sl; n < cnt; n += 8) {
        float v = p[(size_t)n * DD];
        sum += v; sq = fmaf(v, v, sq);
    }
    ssum[sl][t & 31] = sum; ssq[sl][t & 31] = sq;
    __syncthreads();
    if (t < 32) {
        if (cnt <= 0) { g_am[g * DD + f] = 0.f; g_wr[g * DD + f] = 0.f; return; }
        float S = 0.f, Q = 0.f;
        #pragma unroll
        for (int i = 0; i < 8; i++) { S += ssum[i][t]; Q += ssq[i][t]; }
        float inv = 1.f / (float)cnt;
        float mean = S * inv;
        float am = alpha[f] * mean;
        float var = fmaf(am, am, fmaf(-2.f * am, mean, Q * inv));
        g_am[g * DD + f] = am;
        g_wr[g * DD + f] = gw[f] * rsqrtf(var + EPSV);
    }
}

// ---------------- normalize + ELU + residual -> out (x) ----------------
__global__ void k_apply(const float* __restrict__ xres, const float* __restrict__ gnb,
                        float* __restrict__ out) {
    int t = blockIdx.x * blockDim.x + threadIdx.x;
    if (t >= NN * 32) return;
    int n = t >> 5, q = t & 31;
    int g = g_batch[n];
    float4 h = ((const float4*)g_h2)[t];
    float4 a = ((const float4*)g_am)[g * 32 + q];
    float4 w = ((const float4*)g_wr)[g * 32 + q];
    float4 b = ((const float4*)gnb)[q];
    float4 r = ((const float4*)xres)[t];
    float4 o;
    float v;
    v = (h.x - a.x) * w.x + b.x; o.x = (v > 0.f ? v : expm1f(v)) + r.x;
    v = (h.y - a.y) * w.y + b.y; o.y = (v > 0.f ? v : expm1f(v)) + r.y;
    v = (h.z - a.z) * w.z + b.z; o.z = (v > 0.f ? v : expm1f(v)) + r.z;
    v = (h.w - a.w) * w.w + b.w; o.w = (v > 0.f ? v : expm1f(v)) + r.w;
    ((float4*)out)[t] = o;
}

// ---------------- global add pool: grid (GG, 4 chunks) x 256 ----------------
__global__ void __launch_bounds__(256) k_pool(const float* __restrict__ x) {
    int g = blockIdx.x;
    int fc = blockIdx.y;
    int t = threadIdx.x;
    int f = fc * 32 + (t & 31), sl = t >> 5;
    int s = g_gptr[g], e = g_gptr[g + 1];
    int cnt = e - s;
    __shared__ float ssum[8][32];
    float sum = 0.f;
    const float* p = x + (size_t)s * DD + f;
    #pragma unroll 4
    for (int n = sl; n < cnt; n += 8) sum += p[(size_t)n * DD];
    ssum[sl][t & 31] = sum;
    __syncthreads();
    if (t < 32) {
        float S = 0.f;
        #pragma unroll
        for (int i = 0; i < 8; i++) S += ssum[i][t];
        g_pool[g * DD + f] = S;
    }
}

// ---------------- MLP head (reads g_pool) ----------------
__global__ void k_mlp(const float* __restrict__ w1, const float* __restrict__ b1,
                      const float* __restrict__ bng, const float* __restrict__ bnb,
                      const float* __restrict__ bnm, const float* __restrict__ bnv,
                      const float* __restrict__ w2, const float* __restrict__ b2,
                      float* __restrict__ out) {
    int g = blockIdx.x, d = threadIdx.x;
    __shared__ float p[DD], z1[DD];
    p[d] = g_pool[g * DD + d];
    __syncthreads();
    float z = b1[d];
    #pragma unroll 4
    for (int k = 0; k < DD; k++) z = fmaf(p[k], w1[k * DD + d], z);
    z = bng[d] * (z - bnm[d]) * rsqrtf(bnv[d] + EPSV) + bnb[d];
    z = z > 0.f ? z : 0.f;
    z1[d] = z;
    __syncthreads();
    if (d < NCLS) {
        float o = b2[d];
        #pragma unroll 4
        for (int k = 0; k < DD; k++) o = fmaf(z1[k], w2[k * NCLS + d], o);
        out[(size_t)NN * DD + g * NCLS + d] = o;
    }
}

// ---------------- launch ----------------
extern "C" void kernel_launch(void* const* d_in, const int* in_sizes, int n_in,
                              void* d_out, int out_size) {
    const float* x0     = (const float*)d_in[0];
    const void*  ei     = d_in[1];
    const void*  batch  = d_in[2];
    const float* conv_w = (const float*)d_in[3];
    const float* conv_b = (const float*)d_in[4];
    const float* gn_w   = (const float*)d_in[5];
    const float* gn_b   = (const float*)d_in[6];
    const float* gn_ms  = (const float*)d_in[7];
    const float* w1     = (const float*)d_in[8];
    const float* b1     = (const float*)d_in[9];
    const float* bng    = (const float*)d_in[10];
    const float* bnb    = (const float*)d_in[11];
    const float* bnm    = (const float*)d_in[12];
    const float* bnv    = (const float*)d_in[13];
    const float* w2     = (const float*)d_in[14];
    const float* b2     = (const float*)d_in[15];
    float* out = (float*)d_out;

    k_detect<<<1, 256>>>((const int*)ei);
    k_init<<<256, 256>>>();
    k_hist<<<(EE + 255) / 256, 256>>>(ei);
    k_cvt_batch<<<(NN + 255) / 256, 256>>>(batch);
    k_scan1<<<NB, 256>>>();
    k_scan2<<<1, 32>>>();
    k_scan3<<<NB, 256>>>();
    k_scatter<<<(EE + 255) / 256, 256>>>(ei);

    const float* xin = x0;
    for (int l = 0; l < LL; l++) {
        k_gemm<<<(NN + 63) / 64, 256>>>(xin, conv_w + (size_t)l * DD * DD);
        k_spmm<<<(NN + 7) / 8, 256>>>(conv_b + (size_t)l * DD);
        k_stats<<<dim3(GG, 4), 256>>>(gn_ms + (size_t)l * DD, gn_w + (size_t)l * DD);
        k_apply<<<(NN * 32 + 255) / 256, 256>>>(xin, gn_b + (size_t)l * DD, out);
        xin = out;
    }
    k_pool<<<dim3(GG, 4), 256>>>(out);
    k_mlp<<<GG, DD>>>(w1, b1, bng, bnb, bnm, bnv, w2, b2, out);
}